// round 10
// baseline (speedup 1.0000x reference)
#include <cuda_runtime.h>
#include <math.h>
#include <stdint.h>

// ---------------- problem constants ----------------
#define BATCH    4
#define SEQLEN   2048
#define D_MODEL  1024
#define D_STATE  64
#define D_CONV   4
#define HEADDIM  64
#define D_INNER  2048
#define NHEADS   32
#define CONV_DIM 2176          // D_INNER + 2*D_STATE
#define D_IN_PROJ 4256         // 2*D_INNER + 2*D_STATE + NHEADS
#define NROWS    (BATCH * SEQLEN)   // 8192
#define NBH      (BATCH * NHEADS)   // 128
#define CHUNK    512
#define NCHUNK   (SEQLEN / CHUNK)   // 4

// ---------------- scratch (static device globals: no allocs allowed) ----------------
__device__ float g_zxbcdt[(size_t)NROWS * D_IN_PROJ];   // 139.5 MB
__device__ float g_xh[(size_t)NROWS * D_INNER];         // 67 MB (post conv+silu)
__device__ float g_Bm[NROWS * D_STATE];
__device__ float g_Cm[NROWS * D_STATE];
__device__ float g_dt[NROWS * NHEADS];
__device__ float g_yscan[(size_t)NROWS * D_INNER];
__device__ float g_y[(size_t)NROWS * D_INNER];          // gated+normed, tf32-rounded
__device__ float g_xr[(size_t)NROWS * D_MODEL];         // x rounded to tf32
__device__ float g_w1r[(size_t)D_MODEL * D_IN_PROJ];    // W_in rounded
__device__ float g_w2r[(size_t)D_INNER * D_MODEL];      // W_out rounded
// chunked-scan scratch (small: 8MB + 8MB + 1MB)
__device__ float g_hchunk[(size_t)NBH * NCHUNK * HEADDIM * D_STATE];
__device__ float g_hin[(size_t)NBH * NCHUNK * HEADDIM * D_STATE];
__device__ float g_P[(size_t)NBH * SEQLEN];

// ---------------- helpers ----------------
__device__ __forceinline__ float to_tf32(float x) {
    uint32_t u;
    asm("cvt.rna.tf32.f32 %0, %1;" : "=r"(u) : "f"(x));
    return __uint_as_float(u);
}
__device__ __forceinline__ uint32_t smem_u32(const void* p) {
    uint32_t a;
    asm("{ .reg .u64 t; cvta.to.shared.u64 t, %1; cvt.u32.u64 %0, t; }" : "=r"(a) : "l"(p));
    return a;
}
__device__ __forceinline__ void mma_tf32(float* d, const uint32_t* a, const uint32_t* b) {
    asm volatile(
        "mma.sync.aligned.m16n8k8.row.col.f32.tf32.tf32.f32 "
        "{%0,%1,%2,%3}, {%4,%5,%6,%7}, {%8,%9}, {%0,%1,%2,%3};\n"
        : "+f"(d[0]), "+f"(d[1]), "+f"(d[2]), "+f"(d[3])
        : "r"(a[0]), "r"(a[1]), "r"(a[2]), "r"(a[3]), "r"(b[0]), "r"(b[1]));
}
__device__ __forceinline__ void cp16(uint32_t dst, const float* src) {
    asm volatile("cp.async.cg.shared.global [%0], [%1], 16;" :: "r"(dst), "l"(src));
}
__device__ __forceinline__ void cp16z(uint32_t dst, const float* src, int vsz) {
    asm volatile("cp.async.cg.shared.global [%0], [%1], 16, %2;" :: "r"(dst), "l"(src), "r"(vsz));
}
#define CP_COMMIT() asm volatile("cp.async.commit_group;" ::: "memory")
#define CP_WAIT1()  asm volatile("cp.async.wait_group 1;" ::: "memory")

// round fp32 -> tf32-in-fp32
__global__ __launch_bounds__(256)
void round_tf32_kernel(const float* __restrict__ src, float* __restrict__ dst, size_t n4) {
    const size_t i = (size_t)blockIdx.x * 256 + threadIdx.x;
    if (i < n4) {
        float4 v = ((const float4*)src)[i];
        v.x = to_tf32(v.x); v.y = to_tf32(v.y); v.z = to_tf32(v.z); v.w = to_tf32(v.w);
        ((float4*)dst)[i] = v;
    }
}

// ================= pipelined tf32 GEMM: CTA 128x256x32, 8 warps 64x64, 3 stages =================
#define GT_BM 128
#define GT_BN 256
#define GT_BK 32
#define A_ST  36                 // As row stride (floats)
#define B_ST  264                // Bs row stride (floats)
#define ST_AF (GT_BM * A_ST)     // 4608
#define ST_BF (GT_BK * B_ST)     // 8448
#define ST_F  (ST_AF + ST_BF)    // 13056 floats / stage
#define NSTAGE 3
#define GEMM_SMEM (ST_F * NSTAGE * 4)   // 156672 B

__global__ __launch_bounds__(256, 1)
void gemm_tf32_pipe(const float* __restrict__ A, const float* __restrict__ Bw,
                    float* __restrict__ C, int M, int N, int K) {
    extern __shared__ float sm[];
    const uint32_t base = smem_u32(sm);

    const int tid  = threadIdx.x;
    const int warp = tid >> 5, lane = tid & 31;
    const int gid  = lane >> 2, tid4 = lane & 3;
    const int bm   = blockIdx.y * GT_BM, bn = blockIdx.x * GT_BN;
    const int wm   = (warp >> 2) * 64;   // 0 or 64
    const int wn   = (warp & 3) * 64;    // 0,64,128,192

    const int am = tid >> 3, ac = tid & 7;
    const int bk = tid >> 6, bc = tid & 63;
    const int bcol = bn + bc * 4;
    const int bvsz = (bcol + 4 <= N) ? 16 : 0;   // all-or-nothing (N%4==0)

    float acc[4][8][4];
#pragma unroll
    for (int mt = 0; mt < 4; mt++)
#pragma unroll
        for (int nt = 0; nt < 8; nt++)
#pragma unroll
            for (int i = 0; i < 4; i++) acc[mt][nt][i] = 0.f;

#define PIPE_LOAD(T)                                                            \
    do {                                                                        \
        const uint32_t _sb = base + (uint32_t)((T) % NSTAGE) * ST_F * 4;        \
        const int _k0 = (T) * GT_BK;                                            \
        _Pragma("unroll")                                                       \
        for (int p = 0; p < 4; p++) {                                           \
            const int m = am + 32 * p;                                          \
            cp16(_sb + (uint32_t)(m * A_ST + ac * 4) * 4,                       \
                 A + (size_t)(bm + m) * K + _k0 + ac * 4);                      \
        }                                                                       \
        _Pragma("unroll")                                                       \
        for (int p = 0; p < 8; p++) {                                           \
            const int kk = bk + 4 * p;                                          \
            cp16z(_sb + (uint32_t)(ST_AF + kk * B_ST + bc * 4) * 4,             \
                  Bw + (size_t)(_k0 + kk) * N + bcol, bvsz);                    \
        }                                                                       \
    } while (0)

    const int nit = K >> 5;
    PIPE_LOAD(0); CP_COMMIT();
    PIPE_LOAD(1); CP_COMMIT();

    for (int t = 0; t < nit; t++) {
        CP_WAIT1();          // buffer t complete
        __syncthreads();     // all warps done computing t-1

        const float* Asb = sm + (t % NSTAGE) * ST_F;
        const float* Bsb = Asb + ST_AF;
#pragma unroll
        for (int ks = 0; ks < GT_BK; ks += 8) {
            uint32_t af[4][4];
#pragma unroll
            for (int mt = 0; mt < 4; mt++) {
                const int m0 = wm + mt * 16 + gid;
                af[mt][0] = __float_as_uint(Asb[(m0)     * A_ST + ks + tid4]);
                af[mt][1] = __float_as_uint(Asb[(m0 + 8) * A_ST + ks + tid4]);
                af[mt][2] = __float_as_uint(Asb[(m0)     * A_ST + ks + tid4 + 4]);
                af[mt][3] = __float_as_uint(Asb[(m0 + 8) * A_ST + ks + tid4 + 4]);
            }
#pragma unroll
            for (int nt = 0; nt < 8; nt++) {
                uint32_t bf[2];
                const int n0 = wn + nt * 8 + gid;
                bf[0] = __float_as_uint(Bsb[(ks + tid4)     * B_ST + n0]);
                bf[1] = __float_as_uint(Bsb[(ks + tid4 + 4) * B_ST + n0]);
#pragma unroll
                for (int mt = 0; mt < 4; mt++)
                    mma_tf32(acc[mt][nt], af[mt], bf);
            }
        }
        if (t + 2 < nit) PIPE_LOAD(t + 2);
        CP_COMMIT();
    }
#undef PIPE_LOAD

#pragma unroll
    for (int mt = 0; mt < 4; mt++)
#pragma unroll
        for (int nt = 0; nt < 8; nt++) {
            const int r0 = bm + wm + mt * 16 + gid;
            const int c0 = bn + wn + nt * 8 + 2 * tid4;
            if (c0 < N) {
                *(float2*)&C[(size_t)r0 * N + c0] =
                    make_float2(acc[mt][nt][0], acc[mt][nt][1]);
                *(float2*)&C[(size_t)(r0 + 8) * N + c0] =
                    make_float2(acc[mt][nt][2], acc[mt][nt][3]);
            }
        }
}

// ---------------- conv1d + silu: rolling-window (R9 version) ----------------
#define CONV_L 128
__global__ __launch_bounds__(256)
void conv_kernel(const float* __restrict__ conv_w, const float* __restrict__ conv_b) {
    const int b  = blockIdx.z;
    const int c  = blockIdx.y * 256 + threadIdx.x;
    const int l0 = blockIdx.x * CONV_L;
    if (c >= CONV_DIM) return;

    const float4 w   = *(const float4*)&conv_w[c * 4];
    const float bias = conv_b[c];
    const float* src = g_zxbcdt + (size_t)(b * SEQLEN) * D_IN_PROJ + D_INNER + c;

    float x3 = 0.f, x2 = 0.f, x1 = 0.f;
    if (l0 >= 3) {
        x3 = src[(size_t)(l0 - 3) * D_IN_PROJ];
        x2 = src[(size_t)(l0 - 2) * D_IN_PROJ];
        x1 = src[(size_t)(l0 - 1) * D_IN_PROJ];
    }

    for (int l = l0; l < l0 + CONV_L; l += 4) {
        const float c0 = src[(size_t)(l + 0) * D_IN_PROJ];
        const float c1 = src[(size_t)(l + 1) * D_IN_PROJ];
        const float c2 = src[(size_t)(l + 2) * D_IN_PROJ];
        const float c3 = src[(size_t)(l + 3) * D_IN_PROJ];

        float out[4];
        {
            float a;
            a = fmaf(x3, w.x, bias); a = fmaf(x2, w.y, a); a = fmaf(x1, w.z, a); a = fmaf(c0, w.w, a);
            out[0] = a / (1.f + expf(-a));
            a = fmaf(x2, w.x, bias); a = fmaf(x1, w.y, a); a = fmaf(c0, w.z, a); a = fmaf(c1, w.w, a);
            out[1] = a / (1.f + expf(-a));
            a = fmaf(x1, w.x, bias); a = fmaf(c0, w.y, a); a = fmaf(c1, w.z, a); a = fmaf(c2, w.w, a);
            out[2] = a / (1.f + expf(-a));
            a = fmaf(c0, w.x, bias); a = fmaf(c1, w.y, a); a = fmaf(c2, w.z, a); a = fmaf(c3, w.w, a);
            out[3] = a / (1.f + expf(-a));
        }

#pragma unroll
        for (int u = 0; u < 4; u++) {
            const int row = b * SEQLEN + l + u;
            if (c < D_INNER)
                g_xh[(size_t)row * D_INNER + c] = out[u];
            else if (c < D_INNER + D_STATE)
                g_Bm[row * D_STATE + (c - D_INNER)] = out[u];
            else
                g_Cm[row * D_STATE + (c - D_INNER - D_STATE)] = out[u];
        }
        x3 = c1; x2 = c2; x1 = c3;
    }
}

// ---------------- dt softplus ----------------
__global__ __launch_bounds__(256)
void dt_kernel(const float* __restrict__ dt_bias) {
    const int idx = blockIdx.x * 256 + threadIdx.x;
    const int row = idx >> 5;
    const int h   = idx & 31;
    const float v = g_zxbcdt[(size_t)row * D_IN_PROJ + D_INNER + CONV_DIM + h] + dt_bias[h];
    g_dt[idx] = (v > 20.f) ? v : log1pf(expf(v));
}

// ================= chunked SSM scan: 4 chunks of 512 =================
// Phase A: per (bh, chunk) local scan with h0=0; writes y_local, decay prefix P,
// and per-chunk final state. 512 blocks -> ~3.5/SM of latency overlap.
__global__ __launch_bounds__(256)
void scan_chunk_kernel(const float* __restrict__ A_log) {
    const int bh = blockIdx.x >> 2;
    const int ck = blockIdx.x & 3;
    const int b  = bh >> 5, h = bh & 31;
    const int t  = threadIdx.x;
    const int p  = t >> 2;
    const int nq = t & 3;
    const float Acoef = -expf(A_log[h]);
    const int s0 = ck * CHUNK;

    const float* Bp = g_Bm + (size_t)(b * SEQLEN + s0) * D_STATE + nq * 16;
    const float* Cp = g_Cm + (size_t)(b * SEQLEN + s0) * D_STATE + nq * 16;
    const float* xp = g_xh + (size_t)(b * SEQLEN + s0) * D_INNER + h * HEADDIM + p;
    const float* dp = g_dt + (size_t)(b * SEQLEN + s0) * NHEADS + h;
    float*       yp = g_yscan + (size_t)(b * SEQLEN + s0) * D_INNER + h * HEADDIM + p;
    float*       Pp = g_P + (size_t)bh * SEQLEN + s0;

    float hs[16];
#pragma unroll
    for (int i = 0; i < 16; i++) hs[i] = 0.f;
    float P = 1.f;

    float B0[16], C0[16], B1[16], C1[16];
    float dt0, x0, dt1, x1;

#define LOADSTEP(BUF_B, BUF_C, BUF_DT, BUF_X, S)                               \
    do {                                                                       \
        const float* _bb = Bp + (size_t)(S) * D_STATE;                         \
        const float* _cc = Cp + (size_t)(S) * D_STATE;                         \
        *(float4*)&(BUF_B)[0]  = *(const float4*)(_bb + 0);                    \
        *(float4*)&(BUF_B)[4]  = *(const float4*)(_bb + 4);                    \
        *(float4*)&(BUF_B)[8]  = *(const float4*)(_bb + 8);                    \
        *(float4*)&(BUF_B)[12] = *(const float4*)(_bb + 12);                   \
        *(float4*)&(BUF_C)[0]  = *(const float4*)(_cc + 0);                    \
        *(float4*)&(BUF_C)[4]  = *(const float4*)(_cc + 4);                    \
        *(float4*)&(BUF_C)[8]  = *(const float4*)(_cc + 8);                    \
        *(float4*)&(BUF_C)[12] = *(const float4*)(_cc + 12);                   \
        (BUF_DT) = dp[(size_t)(S) * NHEADS];                                   \
        (BUF_X)  = xp[(size_t)(S) * D_INNER];                                  \
    } while (0)

#define COMPSTEP(BUF_B, BUF_C, BUF_DT, BUF_X, S)                               \
    do {                                                                       \
        const float dA  = expf((BUF_DT) * Acoef);                              \
        P *= dA;                                                               \
        const float dtx = (BUF_DT) * (BUF_X);                                  \
        float acc = 0.f;                                                       \
        _Pragma("unroll")                                                      \
        for (int i = 0; i < 16; i++) {                                         \
            hs[i] = fmaf(hs[i], dA, dtx * (BUF_B)[i]);                         \
            acc   = fmaf(hs[i], (BUF_C)[i], acc);                              \
        }                                                                      \
        acc += __shfl_xor_sync(0xffffffffu, acc, 1);                           \
        acc += __shfl_xor_sync(0xffffffffu, acc, 2);                           \
        if (nq == 0) yp[(size_t)(S) * D_INNER] = acc;                          \
        if (t == 0)  Pp[(S)] = P;                                              \
    } while (0)

    LOADSTEP(B0, C0, dt0, x0, 0);
    for (int s = 0; s < CHUNK; s += 2) {
        LOADSTEP(B1, C1, dt1, x1, s + 1);
        COMPSTEP(B0, C0, dt0, x0, s);
        if (s + 2 < CHUNK) LOADSTEP(B0, C0, dt0, x0, s + 2);
        COMPSTEP(B1, C1, dt1, x1, s + 1);
    }
#undef LOADSTEP
#undef COMPSTEP

    float* hc = g_hchunk + ((size_t)(bh * NCHUNK + ck) * HEADDIM + p) * D_STATE + nq * 16;
    *(float4*)&hc[0]  = *(float4*)&hs[0];
    *(float4*)&hc[4]  = *(float4*)&hs[4];
    *(float4*)&hc[8]  = *(float4*)&hs[8];
    *(float4*)&hc[12] = *(float4*)&hs[12];
}

// Phase B: per bh, combine 4 chunk states -> h_in per chunk.
__global__ __launch_bounds__(256)
void scan_combine_kernel() {
    const int bh = blockIdx.x;
    const int p  = threadIdx.x >> 2;
    const int nq = threadIdx.x & 3;
    const size_t eo = ((size_t)p) * D_STATE + nq * 16;

    float hin[16];
#pragma unroll
    for (int i = 0; i < 16; i++) hin[i] = 0.f;

    for (int c = 0; c < NCHUNK; c++) {
        const size_t base = (size_t)(bh * NCHUNK + c) * HEADDIM * D_STATE + eo;
        if (c > 0) {
            float* hi = g_hin + base;
            *(float4*)&hi[0]  = *(float4*)&hin[0];
            *(float4*)&hi[4]  = *(float4*)&hin[4];
            *(float4*)&hi[8]  = *(float4*)&hin[8];
            *(float4*)&hi[12] = *(float4*)&hin[12];
        }
        if (c + 1 < NCHUNK) {
            const float Pt = g_P[(size_t)bh * SEQLEN + c * CHUNK + CHUNK - 1];
            const float* hc = g_hchunk + base;
#pragma unroll
            for (int i = 0; i < 16; i++)
                hin[i] = fmaf(Pt, hin[i], hc[i]);
        }
    }
}

// Phase C: y[t] += P_t * (C_t . h_in[chunk])  for chunks 1..3
__global__ __launch_bounds__(256)
void scan_correct_kernel() {
    const int bh = blockIdx.x / (NCHUNK - 1);
    const int ck = blockIdx.x % (NCHUNK - 1) + 1;
    const int b  = bh >> 5, h = bh & 31;
    const int p  = threadIdx.x >> 2;
    const int nq = threadIdx.x & 3;
    const int s0 = ck * CHUNK;

    float hin[16];
    {
        const float* hi = g_hin + (size_t)(bh * NCHUNK + ck) * HEADDIM * D_STATE
                          + (size_t)p * D_STATE + nq * 16;
        *(float4*)&hin[0]  = *(const float4*)&hi[0];
        *(float4*)&hin[4]  = *(const float4*)&hi[4];
        *(float4*)&hin[8]  = *(const float4*)&hi[8];
        *(float4*)&hin[12] = *(const float4*)&hi[12];
    }

    const float* Cp = g_Cm + (size_t)(b * SEQLEN + s0) * D_STATE + nq * 16;
    const float* Pp = g_P + (size_t)bh * SEQLEN + s0;
    float*       yp = g_yscan + (size_t)(b * SEQLEN + s0) * D_INNER + h * HEADDIM + p;

    float Cv0[16], Cv1[16];
    float P0, P1;

#define LOAD_C(BUF, BP, S)                                                     \
    do {                                                                       \
        const float* _cc = Cp + (size_t)(S) * D_STATE;                         \
        *(float4*)&(BUF)[0]  = *(const float4*)(_cc + 0);                      \
        *(float4*)&(BUF)[4]  = *(const float4*)(_cc + 4);                      \
        *(float4*)&(BUF)[8]  = *(const float4*)(_cc + 8);                      \
        *(float4*)&(BUF)[12] = *(const float4*)(_cc + 12);                     \
        (BP) = Pp[(S)];                                                        \
    } while (0)

#define CORR(BUF, BP, S)                                                       \
    do {                                                                       \
        float a0 = 0.f, a1 = 0.f;                                              \
        _Pragma("unroll")                                                      \
        for (int i = 0; i < 8; i++) {                                          \
            a0 = fmaf(hin[i],     (BUF)[i],     a0);                           \
            a1 = fmaf(hin[i + 8], (BUF)[i + 8], a1);                           \
        }                                                                      \
        float acc = a0 + a1;                                                   \
        acc += __shfl_xor_sync(0xffffffffu, acc, 1);                           \
        acc += __shfl_xor_sync(0xffffffffu, acc, 2);                           \
        if (nq == 0) yp[(size_t)(S) * D_INNER] += acc * (BP);                  \
    } while (0)

    LOAD_C(Cv0, P0, 0);
    for (int s = 0; s < CHUNK; s += 2) {
        LOAD_C(Cv1, P1, s + 1);
        CORR(Cv0, P0, s);
        if (s + 2 < CHUNK) LOAD_C(Cv0, P0, s + 2);
        CORR(Cv1, P1, s + 1);
    }
#undef LOAD_C
#undef CORR
}

// ---------------- gate + RMSNorm (emits tf32-rounded y) ----------------
__global__ __launch_bounds__(256)
void gate_norm_kernel(const float* __restrict__ Dv, const float* __restrict__ norm_w) {
    const int row = blockIdx.x;
    const size_t base = (size_t)row * D_INNER;

    float vals[8];
    float ss = 0.f;
#pragma unroll
    for (int i = 0; i < 8; i++) {
        const int c = threadIdx.x + i * 256;
        const float yv = g_yscan[base + c] + g_xh[base + c] * Dv[c >> 6];
        const float z  = g_zxbcdt[(size_t)row * D_IN_PROJ + c];
        const float y  = yv * (z / (1.f + expf(-z)));
        vals[i] = y;
        ss = fmaf(y, y, ss);
    }
#pragma unroll
    for (int o = 16; o > 0; o >>= 1) ss += __shfl_xor_sync(0xffffffffu, ss, o);
    __shared__ float wsum[8];
    if ((threadIdx.x & 31) == 0) wsum[threadIdx.x >> 5] = ss;
    __syncthreads();
    float tot = 0.f;
#pragma unroll
    for (int w = 0; w < 8; w++) tot += wsum[w];
    const float inv = rsqrtf(tot * (1.f / D_INNER) + 1e-5f);
#pragma unroll
    for (int i = 0; i < 8; i++) {
        const int c = threadIdx.x + i * 256;
        g_y[base + c] = to_tf32(vals[i] * inv * norm_w[c]);
    }
}

// ---------------- launch ----------------
extern "C" void kernel_launch(void* const* d_in, const int* in_sizes, int n_in,
                              void* d_out, int out_size) {
    (void)in_sizes; (void)n_in; (void)out_size;
    const float* x       = (const float*)d_in[0];
    const float* W_in    = (const float*)d_in[1];
    const float* conv_w  = (const float*)d_in[2];
    const float* conv_b  = (const float*)d_in[3];
    const float* dt_bias = (const float*)d_in[4];
    const float* A_log   = (const float*)d_in[5];
    const float* Dv      = (const float*)d_in[6];
    const float* norm_w  = (const float*)d_in[7];
    const float* W_out   = (const float*)d_in[8];
    float* out = (float*)d_out;

    float *zx, *yv, *xr, *w1r, *w2r;
    cudaGetSymbolAddress((void**)&zx,  g_zxbcdt);
    cudaGetSymbolAddress((void**)&yv,  g_y);
    cudaGetSymbolAddress((void**)&xr,  g_xr);
    cudaGetSymbolAddress((void**)&w1r, g_w1r);
    cudaGetSymbolAddress((void**)&w2r, g_w2r);

    cudaFuncSetAttribute(gemm_tf32_pipe, cudaFuncAttributeMaxDynamicSharedMemorySize, GEMM_SMEM);

    // 0) round operands to tf32-in-fp32
    {
        const size_t nx = (size_t)NROWS * D_MODEL / 4;
        round_tf32_kernel<<<(unsigned)((nx + 255) / 256), 256>>>(x, xr, nx);
        const size_t n1 = (size_t)D_MODEL * D_IN_PROJ / 4;
        round_tf32_kernel<<<(unsigned)((n1 + 255) / 256), 256>>>(W_in, w1r, n1);
        const size_t n2 = (size_t)D_INNER * D_MODEL / 4;
        round_tf32_kernel<<<(unsigned)((n2 + 255) / 256), 256>>>(W_out, w2r, n2);
    }

    // 1) zxbcdt = x @ W_in
    {
        dim3 g((D_IN_PROJ + GT_BN - 1) / GT_BN, NROWS / GT_BM);
        gemm_tf32_pipe<<<g, 256, GEMM_SMEM>>>(xr, w1r, zx, NROWS, D_IN_PROJ, D_MODEL);
    }

    // 2) conv + silu (rolling window), dt softplus
    {
        dim3 gc(SEQLEN / CONV_L, (CONV_DIM + 255) / 256, BATCH);
        conv_kernel<<<gc, 256>>>(conv_w, conv_b);
        dt_kernel<<<(NROWS * NHEADS) / 256, 256>>>(dt_bias);
    }

    // 3) chunked SSM scan (4 chunks of 512)
    scan_chunk_kernel<<<NBH * NCHUNK, 256>>>(A_log);
    scan_combine_kernel<<<NBH, 256>>>();
    scan_correct_kernel<<<NBH * (NCHUNK - 1), 256>>>();

    // 4) gate + RMSNorm
    gate_norm_kernel<<<NROWS, 256>>>(Dv, norm_w);

    // 5) out = y @ W_out
    {
        dim3 g(D_MODEL / GT_BN, NROWS / GT_BM);
        gemm_tf32_pipe<<<g, 256, GEMM_SMEM>>>(yv, w2r, out, NROWS, D_MODEL, D_INNER);
    }
}

// round 11
// speedup vs baseline: 1.0807x; 1.0807x over previous
#include <cuda_runtime.h>
#include <math.h>
#include <stdint.h>

// ---------------- problem constants ----------------
#define BATCH    4
#define SEQLEN   2048
#define D_MODEL  1024
#define D_STATE  64
#define D_CONV   4
#define HEADDIM  64
#define D_INNER  2048
#define NHEADS   32
#define CONV_DIM 2176          // D_INNER + 2*D_STATE
#define D_IN_PROJ 4256         // 2*D_INNER + 2*D_STATE + NHEADS
#define NROWS    (BATCH * SEQLEN)   // 8192

// ---------------- scratch (static device globals: no allocs allowed) ----------------
__device__ float g_zxbcdt[(size_t)NROWS * D_IN_PROJ];   // 139.5 MB
__device__ float g_xh[(size_t)NROWS * D_INNER];         // 67 MB (post conv+silu)
__device__ float g_Bm[NROWS * D_STATE];
__device__ float g_Cm[NROWS * D_STATE];
__device__ float g_dt[NROWS * NHEADS];
__device__ float g_yscan[(size_t)NROWS * D_INNER];
__device__ float g_y[(size_t)NROWS * D_INNER];          // gated+normed, tf32-rounded
__device__ float g_xr[(size_t)NROWS * D_MODEL];         // x rounded to tf32
__device__ float g_w1r[(size_t)D_MODEL * D_IN_PROJ];    // W_in rounded
__device__ float g_w2r[(size_t)D_INNER * D_MODEL];      // W_out rounded

// ---------------- helpers ----------------
__device__ __forceinline__ float to_tf32(float x) {
    uint32_t u;
    asm("cvt.rna.tf32.f32 %0, %1;" : "=r"(u) : "f"(x));
    return __uint_as_float(u);
}
__device__ __forceinline__ uint32_t smem_u32(const void* p) {
    uint32_t a;
    asm("{ .reg .u64 t; cvta.to.shared.u64 t, %1; cvt.u32.u64 %0, t; }" : "=r"(a) : "l"(p));
    return a;
}
__device__ __forceinline__ void mma_tf32(float* d, const uint32_t* a, const uint32_t* b) {
    asm volatile(
        "mma.sync.aligned.m16n8k8.row.col.f32.tf32.tf32.f32 "
        "{%0,%1,%2,%3}, {%4,%5,%6,%7}, {%8,%9}, {%0,%1,%2,%3};\n"
        : "+f"(d[0]), "+f"(d[1]), "+f"(d[2]), "+f"(d[3])
        : "r"(a[0]), "r"(a[1]), "r"(a[2]), "r"(a[3]), "r"(b[0]), "r"(b[1]));
}
__device__ __forceinline__ void cp16(uint32_t dst, const float* src) {
    asm volatile("cp.async.cg.shared.global [%0], [%1], 16;" :: "r"(dst), "l"(src));
}
__device__ __forceinline__ void cp16z(uint32_t dst, const float* src, int vsz) {
    asm volatile("cp.async.cg.shared.global [%0], [%1], 16, %2;" :: "r"(dst), "l"(src), "r"(vsz));
}
#define CP_COMMIT() asm volatile("cp.async.commit_group;" ::: "memory")
#define CP_WAIT1()  asm volatile("cp.async.wait_group 1;" ::: "memory")
#define CP_WAIT0()  asm volatile("cp.async.wait_group 0;" ::: "memory")

// round fp32 -> tf32-in-fp32
__global__ __launch_bounds__(256)
void round_tf32_kernel(const float* __restrict__ src, float* __restrict__ dst, size_t n4) {
    const size_t i = (size_t)blockIdx.x * 256 + threadIdx.x;
    if (i < n4) {
        float4 v = ((const float4*)src)[i];
        v.x = to_tf32(v.x); v.y = to_tf32(v.y); v.z = to_tf32(v.z); v.w = to_tf32(v.w);
        ((float4*)dst)[i] = v;
    }
}

// ================= pipelined tf32 GEMM: CTA 128x256x64, 8 warps 64x64, 2 stages =================
#define GT_BM 128
#define GT_BN 256
#define GT_BK 64
#define A_ST  68                 // As row stride (floats): (4*gid+tid4)%32 distinct
#define B_ST  264                // Bs row stride (floats): (8*tid4+gid)%32 distinct
#define ST_AF (GT_BM * A_ST)     // 8704
#define ST_BF (GT_BK * B_ST)     // 16896
#define ST_F  (ST_AF + ST_BF)    // 25600 floats / stage
#define NSTAGE 2
#define GEMM_SMEM (ST_F * NSTAGE * 4)   // 204800 B

__global__ __launch_bounds__(256, 1)
void gemm_tf32_pipe(const float* __restrict__ A, const float* __restrict__ Bw,
                    float* __restrict__ C, int M, int N, int K) {
    extern __shared__ float sm[];
    const uint32_t base = smem_u32(sm);

    const int tid  = threadIdx.x;
    const int warp = tid >> 5, lane = tid & 31;
    const int gid  = lane >> 2, tid4 = lane & 3;
    const int bm   = blockIdx.y * GT_BM, bn = blockIdx.x * GT_BN;
    const int wm   = (warp >> 2) * 64;   // 0 or 64
    const int wn   = (warp & 3) * 64;    // 0,64,128,192

    // cp.async mapping (BK=64):
    // A: 128 rows x 16 chunks -> thread (am = tid>>4, ac = tid&15), rows am+16p, p<8
    // B: 64 rows x 64 chunks  -> thread (bk = tid>>6, bc = tid&63), rows bk+4p, p<16
    const int am = tid >> 4, ac = tid & 15;
    const int bk = tid >> 6, bc = tid & 63;
    const int bcol = bn + bc * 4;
    const int bvsz = (bcol + 4 <= N) ? 16 : 0;   // all-or-nothing (N%4==0)

    float acc[4][8][4];
#pragma unroll
    for (int mt = 0; mt < 4; mt++)
#pragma unroll
        for (int nt = 0; nt < 8; nt++)
#pragma unroll
            for (int i = 0; i < 4; i++) acc[mt][nt][i] = 0.f;

#define PIPE_LOAD(T)                                                            \
    do {                                                                        \
        const uint32_t _sb = base + (uint32_t)((T) & 1) * ST_F * 4;             \
        const int _k0 = (T) * GT_BK;                                            \
        _Pragma("unroll")                                                       \
        for (int p = 0; p < 8; p++) {                                           \
            const int m = am + 16 * p;                                          \
            cp16(_sb + (uint32_t)(m * A_ST + ac * 4) * 4,                       \
                 A + (size_t)(bm + m) * K + _k0 + ac * 4);                      \
        }                                                                       \
        _Pragma("unroll")                                                       \
        for (int p = 0; p < 16; p++) {                                          \
            const int kk = bk + 4 * p;                                          \
            cp16z(_sb + (uint32_t)(ST_AF + kk * B_ST + bc * 4) * 4,             \
                  Bw + (size_t)(_k0 + kk) * N + bcol, bvsz);                    \
        }                                                                       \
    } while (0)

    const int nit = K / GT_BK;
    PIPE_LOAD(0); CP_COMMIT();

    for (int t = 0; t < nit; t++) {
        // buffer (t+1)&1 held tile t-1, fully consumed (sync at end of prev iter)
        if (t + 1 < nit) { PIPE_LOAD(t + 1); CP_COMMIT(); CP_WAIT1(); }
        else             { CP_WAIT0(); }
        __syncthreads();

        const float* Asb = sm + (t & 1) * ST_F;
        const float* Bsb = Asb + ST_AF;
#pragma unroll
        for (int ks = 0; ks < GT_BK; ks += 8) {
            uint32_t af[4][4];
#pragma unroll
            for (int mt = 0; mt < 4; mt++) {
                const int m0 = wm + mt * 16 + gid;
                af[mt][0] = __float_as_uint(Asb[(m0)     * A_ST + ks + tid4]);
                af[mt][1] = __float_as_uint(Asb[(m0 + 8) * A_ST + ks + tid4]);
                af[mt][2] = __float_as_uint(Asb[(m0)     * A_ST + ks + tid4 + 4]);
                af[mt][3] = __float_as_uint(Asb[(m0 + 8) * A_ST + ks + tid4 + 4]);
            }
#pragma unroll
            for (int nt = 0; nt < 8; nt++) {
                uint32_t bf[2];
                const int n0 = wn + nt * 8 + gid;
                bf[0] = __float_as_uint(Bsb[(ks + tid4)     * B_ST + n0]);
                bf[1] = __float_as_uint(Bsb[(ks + tid4 + 4) * B_ST + n0]);
#pragma unroll
                for (int mt = 0; mt < 4; mt++)
                    mma_tf32(acc[mt][nt], af[mt], bf);
            }
        }
        __syncthreads();   // all warps done with this buffer before it is refilled
    }
#undef PIPE_LOAD

#pragma unroll
    for (int mt = 0; mt < 4; mt++)
#pragma unroll
        for (int nt = 0; nt < 8; nt++) {
            const int r0 = bm + wm + mt * 16 + gid;
            const int c0 = bn + wn + nt * 8 + 2 * tid4;
            if (c0 < N) {
                *(float2*)&C[(size_t)r0 * N + c0] =
                    make_float2(acc[mt][nt][0], acc[mt][nt][1]);
                *(float2*)&C[(size_t)(r0 + 8) * N + c0] =
                    make_float2(acc[mt][nt][2], acc[mt][nt][3]);
            }
        }
}

// ---------------- conv1d + silu: rolling-window (R9 version) ----------------
#define CONV_L 128
__global__ __launch_bounds__(256)
void conv_kernel(const float* __restrict__ conv_w, const float* __restrict__ conv_b) {
    const int b  = blockIdx.z;
    const int c  = blockIdx.y * 256 + threadIdx.x;
    const int l0 = blockIdx.x * CONV_L;
    if (c >= CONV_DIM) return;

    const float4 w   = *(const float4*)&conv_w[c * 4];
    const float bias = conv_b[c];
    const float* src = g_zxbcdt + (size_t)(b * SEQLEN) * D_IN_PROJ + D_INNER + c;

    float x3 = 0.f, x2 = 0.f, x1 = 0.f;
    if (l0 >= 3) {
        x3 = src[(size_t)(l0 - 3) * D_IN_PROJ];
        x2 = src[(size_t)(l0 - 2) * D_IN_PROJ];
        x1 = src[(size_t)(l0 - 1) * D_IN_PROJ];
    }

    for (int l = l0; l < l0 + CONV_L; l += 4) {
        const float c0 = src[(size_t)(l + 0) * D_IN_PROJ];
        const float c1 = src[(size_t)(l + 1) * D_IN_PROJ];
        const float c2 = src[(size_t)(l + 2) * D_IN_PROJ];
        const float c3 = src[(size_t)(l + 3) * D_IN_PROJ];

        float out[4];
        {
            float a;
            a = fmaf(x3, w.x, bias); a = fmaf(x2, w.y, a); a = fmaf(x1, w.z, a); a = fmaf(c0, w.w, a);
            out[0] = a / (1.f + expf(-a));
            a = fmaf(x2, w.x, bias); a = fmaf(x1, w.y, a); a = fmaf(c0, w.z, a); a = fmaf(c1, w.w, a);
            out[1] = a / (1.f + expf(-a));
            a = fmaf(x1, w.x, bias); a = fmaf(c0, w.y, a); a = fmaf(c1, w.z, a); a = fmaf(c2, w.w, a);
            out[2] = a / (1.f + expf(-a));
            a = fmaf(c0, w.x, bias); a = fmaf(c1, w.y, a); a = fmaf(c2, w.z, a); a = fmaf(c3, w.w, a);
            out[3] = a / (1.f + expf(-a));
        }

#pragma unroll
        for (int u = 0; u < 4; u++) {
            const int row = b * SEQLEN + l + u;
            if (c < D_INNER)
                g_xh[(size_t)row * D_INNER + c] = out[u];
            else if (c < D_INNER + D_STATE)
                g_Bm[row * D_STATE + (c - D_INNER)] = out[u];
            else
                g_Cm[row * D_STATE + (c - D_INNER - D_STATE)] = out[u];
        }
        x3 = c1; x2 = c2; x1 = c3;
    }
}

// ---------------- dt softplus ----------------
__global__ __launch_bounds__(256)
void dt_kernel(const float* __restrict__ dt_bias) {
    const int idx = blockIdx.x * 256 + threadIdx.x;
    const int row = idx >> 5;
    const int h   = idx & 31;
    const float v = g_zxbcdt[(size_t)row * D_IN_PROJ + D_INNER + CONV_DIM + h] + dt_bias[h];
    g_dt[idx] = (v > 20.f) ? v : log1pf(expf(v));
}

// ---------------- sequential SSM scan (R4/R9 version) ----------------
__global__ __launch_bounds__(256)
void scan_kernel(const float* __restrict__ A_log, float* __restrict__ yscan) {
    const int b  = blockIdx.x >> 5;
    const int h  = blockIdx.x & 31;
    const int t  = threadIdx.x;
    const int p  = t >> 2;
    const int nq = t & 3;
    const float Acoef = -expf(A_log[h]);

    const float* Bp = g_Bm + (size_t)b * SEQLEN * D_STATE + nq * 16;
    const float* Cp = g_Cm + (size_t)b * SEQLEN * D_STATE + nq * 16;
    const float* xp = g_xh + (size_t)b * SEQLEN * D_INNER + h * HEADDIM + p;
    const float* dp = g_dt + (size_t)b * SEQLEN * NHEADS + h;
    float*       yp = yscan + (size_t)b * SEQLEN * D_INNER + h * HEADDIM + p;

    float hs[16];
#pragma unroll
    for (int i = 0; i < 16; i++) hs[i] = 0.f;

    float B0[16], C0[16], B1[16], C1[16];
    float dt0, x0, dt1, x1;

#define LOADSTEP(BUF_B, BUF_C, BUF_DT, BUF_X, S)                               \
    do {                                                                       \
        const float* _bb = Bp + (size_t)(S) * D_STATE;                         \
        const float* _cc = Cp + (size_t)(S) * D_STATE;                         \
        *(float4*)&(BUF_B)[0]  = *(const float4*)(_bb + 0);                    \
        *(float4*)&(BUF_B)[4]  = *(const float4*)(_bb + 4);                    \
        *(float4*)&(BUF_B)[8]  = *(const float4*)(_bb + 8);                    \
        *(float4*)&(BUF_B)[12] = *(const float4*)(_bb + 12);                   \
        *(float4*)&(BUF_C)[0]  = *(const float4*)(_cc + 0);                    \
        *(float4*)&(BUF_C)[4]  = *(const float4*)(_cc + 4);                    \
        *(float4*)&(BUF_C)[8]  = *(const float4*)(_cc + 8);                    \
        *(float4*)&(BUF_C)[12] = *(const float4*)(_cc + 12);                   \
        (BUF_DT) = dp[(size_t)(S) * NHEADS];                                   \
        (BUF_X)  = xp[(size_t)(S) * D_INNER];                                  \
    } while (0)

#define COMPSTEP(BUF_B, BUF_C, BUF_DT, BUF_X, S)                               \
    do {                                                                       \
        const float dA  = expf((BUF_DT) * Acoef);                              \
        const float dtx = (BUF_DT) * (BUF_X);                                  \
        float acc = 0.f;                                                       \
        _Pragma("unroll")                                                      \
        for (int i = 0; i < 16; i++) {                                         \
            hs[i] = fmaf(hs[i], dA, dtx * (BUF_B)[i]);                         \
            acc   = fmaf(hs[i], (BUF_C)[i], acc);                              \
        }                                                                      \
        acc += __shfl_xor_sync(0xffffffffu, acc, 1);                           \
        acc += __shfl_xor_sync(0xffffffffu, acc, 2);                           \
        if (nq == 0) yp[(size_t)(S) * D_INNER] = acc;                          \
    } while (0)

    LOADSTEP(B0, C0, dt0, x0, 0);
    for (int s = 0; s < SEQLEN; s += 2) {
        LOADSTEP(B1, C1, dt1, x1, s + 1);
        COMPSTEP(B0, C0, dt0, x0, s);
        if (s + 2 < SEQLEN) LOADSTEP(B0, C0, dt0, x0, s + 2);
        COMPSTEP(B1, C1, dt1, x1, s + 1);
    }
#undef LOADSTEP
#undef COMPSTEP
}

// ---------------- gate + RMSNorm (emits tf32-rounded y) ----------------
__global__ __launch_bounds__(256)
void gate_norm_kernel(const float* __restrict__ Dv, const float* __restrict__ norm_w) {
    const int row = blockIdx.x;
    const size_t base = (size_t)row * D_INNER;

    float vals[8];
    float ss = 0.f;
#pragma unroll
    for (int i = 0; i < 8; i++) {
        const int c = threadIdx.x + i * 256;
        const float yv = g_yscan[base + c] + g_xh[base + c] * Dv[c >> 6];
        const float z  = g_zxbcdt[(size_t)row * D_IN_PROJ + c];
        const float y  = yv * (z / (1.f + expf(-z)));
        vals[i] = y;
        ss = fmaf(y, y, ss);
    }
#pragma unroll
    for (int o = 16; o > 0; o >>= 1) ss += __shfl_xor_sync(0xffffffffu, ss, o);
    __shared__ float wsum[8];
    if ((threadIdx.x & 31) == 0) wsum[threadIdx.x >> 5] = ss;
    __syncthreads();
    float tot = 0.f;
#pragma unroll
    for (int w = 0; w < 8; w++) tot += wsum[w];
    const float inv = rsqrtf(tot * (1.f / D_INNER) + 1e-5f);
#pragma unroll
    for (int i = 0; i < 8; i++) {
        const int c = threadIdx.x + i * 256;
        g_y[base + c] = to_tf32(vals[i] * inv * norm_w[c]);
    }
}

// ---------------- launch ----------------
extern "C" void kernel_launch(void* const* d_in, const int* in_sizes, int n_in,
                              void* d_out, int out_size) {
    (void)in_sizes; (void)n_in; (void)out_size;
    const float* x       = (const float*)d_in[0];
    const float* W_in    = (const float*)d_in[1];
    const float* conv_w  = (const float*)d_in[2];
    const float* conv_b  = (const float*)d_in[3];
    const float* dt_bias = (const float*)d_in[4];
    const float* A_log   = (const float*)d_in[5];
    const float* Dv      = (const float*)d_in[6];
    const float* norm_w  = (const float*)d_in[7];
    const float* W_out   = (const float*)d_in[8];
    float* out = (float*)d_out;

    float *zx, *ys, *yv, *xr, *w1r, *w2r;
    cudaGetSymbolAddress((void**)&zx,  g_zxbcdt);
    cudaGetSymbolAddress((void**)&ys,  g_yscan);
    cudaGetSymbolAddress((void**)&yv,  g_y);
    cudaGetSymbolAddress((void**)&xr,  g_xr);
    cudaGetSymbolAddress((void**)&w1r, g_w1r);
    cudaGetSymbolAddress((void**)&w2r, g_w2r);

    cudaFuncSetAttribute(gemm_tf32_pipe, cudaFuncAttributeMaxDynamicSharedMemorySize, GEMM_SMEM);

    // 0) round operands to tf32-in-fp32
    {
        const size_t nx = (size_t)NROWS * D_MODEL / 4;
        round_tf32_kernel<<<(unsigned)((nx + 255) / 256), 256>>>(x, xr, nx);
        const size_t n1 = (size_t)D_MODEL * D_IN_PROJ / 4;
        round_tf32_kernel<<<(unsigned)((n1 + 255) / 256), 256>>>(W_in, w1r, n1);
        const size_t n2 = (size_t)D_INNER * D_MODEL / 4;
        round_tf32_kernel<<<(unsigned)((n2 + 255) / 256), 256>>>(W_out, w2r, n2);
    }

    // 1) zxbcdt = x @ W_in   [8192 x 4256], K=1024
    {
        dim3 g((D_IN_PROJ + GT_BN - 1) / GT_BN, NROWS / GT_BM);
        gemm_tf32_pipe<<<g, 256, GEMM_SMEM>>>(xr, w1r, zx, NROWS, D_IN_PROJ, D_MODEL);
    }

    // 2) conv + silu (rolling window), dt softplus
    {
        dim3 gc(SEQLEN / CONV_L, (CONV_DIM + 255) / 256, BATCH);
        conv_kernel<<<gc, 256>>>(conv_w, conv_b);
        dt_kernel<<<(NROWS * NHEADS) / 256, 256>>>(dt_bias);
    }

    // 3) SSM scan (serial)
    scan_kernel<<<BATCH * NHEADS, 256>>>(A_log, ys);

    // 4) gate + RMSNorm
    gate_norm_kernel<<<NROWS, 256>>>(Dv, norm_w);

    // 5) out = y @ W_out   [8192 x 1024], K=2048
    {
        dim3 g(D_MODEL / GT_BN, NROWS / GT_BM);
        gemm_tf32_pipe<<<g, 256, GEMM_SMEM>>>(yv, w2r, out, NROWS, D_MODEL, D_INNER);
    }
}